// round 14
// baseline (speedup 1.0000x reference)
#include <cuda_runtime.h>
#include <cuda_fp16.h>
#include <cstdint>

// ============================================================================
// QuantizedLinear: y[M,N] = (x[M,K] @ W_int8[N,K]^T) / 127
//   M=8192, N=4096, K=4096. sm_103 legacy tensor path.
//
//   Round 13 = Round 12 (WIN: CTA 128x128, 8 compute warps 32x64, 2 CTAs/SM,
//   4 warps/SMSP from 2 independent CTAs, 96 regs, GEMM 556us) +
//   A-fragment-only double buffering: +8 regs (~104 <= 112 cap, 8 headroom).
//   loadA(ks+1) issues before mma(ks) -> A-load/MMA serialization removed.
//   Barrier protocol and B addressing unchanged (r6-validated pattern).
// ============================================================================

#define KDIM 4096
#define NDIM 4096
#define MDIM 8192
#define BM   128
#define BN   128
#define BK   64
#define NKT  (KDIM / BK)          // 64
#define STAGES 3

#define A_TILE_BYTES (BM * BK * 2)                  // 16384
#define B_TILE_BYTES (BN * BK * 2)                  // 16384
#define STAGE_BYTES  (A_TILE_BYTES + B_TILE_BYTES)  // 32768
#define TILES_OFF    1024
#define SMEM_BYTES   (TILES_OFF + STAGES * STAGE_BYTES)  // 99328 (x2 < 228K)

#define NTHREADS 288   // 8 compute warps + 1 producer warp

#define SCALE (1.0f / 127.0f)

// pre-swizzled fp16 tile scratch (device globals: allocation-free)
__device__ __half g_W[(size_t)NDIM * KDIM];   // 32 MB, tiles [nt][kt][128x64]
__device__ __half g_A[(size_t)MDIM * KDIM];   // 64 MB, tiles [mt][kt][128x64]

__host__ __device__ __forceinline__ uint32_t swz128(uint32_t off) {
    return off ^ ((off >> 3) & 0x70);
}

__device__ __forceinline__ uint32_t pack_h2(float a, float b) {
    __half2 t;
    t.x = __float2half_rn(a);
    t.y = __float2half_rn(b);
    return *reinterpret_cast<uint32_t*>(&t);
}

// ---------------------------------------------------------------------------
// Merged prep: W int32 -> fp16 tiles, x fp32 -> fp16 tiles (SW128 pre-applied)
// Streaming loads/stores: all data here is touched exactly once.
// ---------------------------------------------------------------------------
#define W_CHUNKS (NDIM * (KDIM / 8))   // 2097152
#define X_CHUNKS (MDIM * (KDIM / 8))   // 4194304

__global__ void k_prep(const int4* __restrict__ w, const float4* __restrict__ x,
                       uint4* __restrict__ Wt, uint4* __restrict__ At) {
    uint32_t t = blockIdx.x * blockDim.x + threadIdx.x;
    if (t < W_CHUNKS) {
        uint32_t n = t >> 9, cg = t & 511;           // 8-elem chunk along K
        int4 v0 = __ldcs(&w[(size_t)n * 1024 + cg * 2]);
        int4 v1 = __ldcs(&w[(size_t)n * 1024 + cg * 2 + 1]);
        uint4 o;
        o.x = pack_h2((float)v0.x, (float)v0.y);
        o.y = pack_h2((float)v0.z, (float)v0.w);
        o.z = pack_h2((float)v1.x, (float)v1.y);
        o.w = pack_h2((float)v1.z, (float)v1.w);
        uint32_t nt = n >> 7, r = n & 127, kt = cg >> 3, c = cg & 7;
        size_t tile_u4 = ((size_t)nt * NKT + kt) * (B_TILE_BYTES / 16);
        __stcs(&Wt[tile_u4 + (swz128(r * 128 + c * 16) >> 4)], o);
    } else {
        t -= W_CHUNKS;
        uint32_t m = t >> 9, cg = t & 511;
        float4 v0 = __ldcs(&x[(size_t)m * 1024 + cg * 2]);
        float4 v1 = __ldcs(&x[(size_t)m * 1024 + cg * 2 + 1]);
        uint4 o;
        o.x = pack_h2(v0.x, v0.y);
        o.y = pack_h2(v0.z, v0.w);
        o.z = pack_h2(v1.x, v1.y);
        o.w = pack_h2(v1.z, v1.w);
        uint32_t mt = m >> 7, r = m & 127, kt = cg >> 3, c = cg & 7;
        size_t tile_u4 = ((size_t)mt * NKT + kt) * (A_TILE_BYTES / 16);
        __stcs(&At[tile_u4 + (swz128(r * 128 + c * 16) >> 4)], o);
    }
}

// ---------------------------------------------------------------------------
// PTX helpers
// ---------------------------------------------------------------------------
__device__ __forceinline__ bool elect_one() {
    uint32_t pred;
    asm volatile("{\n\t.reg .pred p;\n\telect.sync _|p, 0xFFFFFFFF;\n\t"
                 "selp.b32 %0, 1, 0, p;\n\t}" : "=r"(pred));
    return pred != 0;
}
__device__ __forceinline__ void mbar_init(uint32_t a, uint32_t cnt) {
    asm volatile("mbarrier.init.shared.b64 [%0], %1;" :: "r"(a), "r"(cnt) : "memory");
}
__device__ __forceinline__ void mbar_expect_tx(uint32_t a, uint32_t bytes) {
    asm volatile("mbarrier.arrive.expect_tx.shared.b64 _, [%0], %1;"
                 :: "r"(a), "r"(bytes) : "memory");
}
__device__ __forceinline__ void mbar_arrive(uint32_t a) {
    asm volatile("mbarrier.arrive.shared.b64 _, [%0];" :: "r"(a) : "memory");
}
__device__ __forceinline__ void mbar_wait(uint32_t a, uint32_t parity) {
    asm volatile(
        "{\n\t.reg .pred P1;\n"
        "WAIT_LOOP_%=:\n\t"
        "mbarrier.try_wait.parity.acquire.cta.shared::cta.b64 P1, [%0], %1, 0x989680;\n\t"
        "@P1 bra.uni WAIT_DONE_%=;\n\t"
        "bra.uni WAIT_LOOP_%=;\n"
        "WAIT_DONE_%=:\n\t}"
        :: "r"(a), "r"(parity) : "memory");
}
__device__ __forceinline__ void bulk_g2s(uint32_t dst, const void* src,
                                         uint32_t bytes, uint32_t mbar) {
    asm volatile(
        "cp.async.bulk.shared::cluster.global.mbarrier::complete_tx::bytes "
        "[%0], [%1], %2, [%3];"
        :: "r"(dst), "l"(src), "r"(bytes), "r"(mbar) : "memory");
}
__device__ __forceinline__ void ldmatrix_x4(uint32_t& r0, uint32_t& r1,
                                            uint32_t& r2, uint32_t& r3, uint32_t a) {
    asm volatile("ldmatrix.sync.aligned.m8n8.x4.shared.b16 {%0,%1,%2,%3}, [%4];"
                 : "=r"(r0), "=r"(r1), "=r"(r2), "=r"(r3) : "r"(a));
}
__device__ __forceinline__ void mma16816(float* c, const uint32_t* a, const uint32_t* b) {
    asm volatile(
        "mma.sync.aligned.m16n8k16.row.col.f32.f16.f16.f32 "
        "{%0,%1,%2,%3}, {%4,%5,%6,%7}, {%8,%9}, {%0,%1,%2,%3};"
        : "+f"(c[0]), "+f"(c[1]), "+f"(c[2]), "+f"(c[3])
        : "r"(a[0]), "r"(a[1]), "r"(a[2]), "r"(a[3]), "r"(b[0]), "r"(b[1]));
}

// ---------------------------------------------------------------------------
// GEMM: 288 threads. Warps 0-7 compute (4x2, warp tile 32x64). Warp 8: producer.
// Two CTAs co-resident per SM; A fragments double-buffered (+8 regs).
// ---------------------------------------------------------------------------
__global__ __launch_bounds__(NTHREADS, 2)
void gemm_kernel(float* __restrict__ C) {
    extern __shared__ char smem[];
    const uint32_t sb = (uint32_t)__cvta_generic_to_shared(smem);
    const int tid  = threadIdx.x;
    const int warp = tid >> 5;
    const int lane = tid & 31;
    const int nt = blockIdx.x;   // 0..31
    const int mt = blockIdx.y;   // 0..63

    const uint32_t mb_full  = sb;        // 3 x 8B
    const uint32_t mb_empty = sb + 32;   // 3 x 8B

    if (tid == 0) {
        #pragma unroll
        for (int s = 0; s < STAGES; s++) {
            mbar_init(mb_full  + 8 * s, 1);   // tx-based completion
            mbar_init(mb_empty + 8 * s, 8);   // lane0 of each compute warp
        }
    }
    __syncthreads();

    if (warp == 8) {
        // ---------------- producer ----------------
        if (elect_one()) {
            const char* pA = (const char*)g_A + (size_t)mt * NKT * A_TILE_BYTES;
            const char* pB = (const char*)g_W + (size_t)nt * NKT * B_TILE_BYTES;
            int s = 0, ph = 1;
            for (int j = 0; j < NKT; j++) {
                mbar_wait(mb_empty + 8 * s, ph);  // 1st pass free (parity 1)
                const uint32_t st = sb + TILES_OFF + s * STAGE_BYTES;
                mbar_expect_tx(mb_full + 8 * s, STAGE_BYTES);
                bulk_g2s(st, pA + (size_t)j * A_TILE_BYTES, A_TILE_BYTES,
                         mb_full + 8 * s);
                bulk_g2s(st + A_TILE_BYTES, pB + (size_t)j * B_TILE_BYTES,
                         B_TILE_BYTES, mb_full + 8 * s);
                if (++s == STAGES) { s = 0; ph ^= 1; }
            }
        }
        return;
    }

    // ---------------- compute warps ----------------
    const int warp_m = warp >> 1;   // 0..3 -> 32 rows each
    const int warp_n = warp & 1;    // 0..1 -> 64 cols each

    // Swizzle collapses to a per-thread constant XOR: low-offset bits
    // (ks*32 + kofs <= 112) never carry into row bits, and row&7 == lane&7.
    const uint32_t xm = (uint32_t)(lane & 7) << 4;
    const uint32_t aK = (uint32_t)(lane >> 4) * 16;          // k-half for A ldmatrix
    const uint32_t bK = (uint32_t)((lane >> 3) & 1) * 16;    // k-half for B ldmatrix
    const uint32_t aBase = (uint32_t)(warp_m * 32 + (lane & 15)) * 128;
    const uint32_t bBase = (uint32_t)(warp_n * 64 + ((lane >> 4) & 1) * 8 + (lane & 7)) * 128;

    float acc[2][8][4];
    #pragma unroll
    for (int mi = 0; mi < 2; mi++)
        #pragma unroll
        for (int ni = 0; ni < 8; ni++)
            #pragma unroll
            for (int r = 0; r < 4; r++) acc[mi][ni][r] = 0.0f;

    uint32_t afr[2][2][4];   // [buf][mi][reg] - double buffered (+8 regs)
    uint32_t bfr[8][2];      // [ni][reg]      - single buffered

    auto loadA = [&](int b, uint32_t sA, int ks) {
        const uint32_t lowA = ((uint32_t)(ks * 32) + aK) ^ xm;
        #pragma unroll
        for (int mi = 0; mi < 2; mi++)
            ldmatrix_x4(afr[b][mi][0], afr[b][mi][1], afr[b][mi][2], afr[b][mi][3],
                        sA + aBase + mi * (16 * 128) + lowA);
    };
    auto loadB = [&](uint32_t sB, int ks) {
        const uint32_t lowB = ((uint32_t)(ks * 32) + bK) ^ xm;
        #pragma unroll
        for (int nj = 0; nj < 4; nj++)
            ldmatrix_x4(bfr[2 * nj][0], bfr[2 * nj][1],
                        bfr[2 * nj + 1][0], bfr[2 * nj + 1][1],
                        sB + bBase + nj * (16 * 128) + lowB);
    };
    auto mma_batch = [&](int b) {
        #pragma unroll
        for (int mi = 0; mi < 2; mi++)
            #pragma unroll
            for (int ni = 0; ni < 8; ni++)
                mma16816(acc[mi][ni], afr[b][mi], bfr[ni]);
    };

    // prologue: stage 0 full, A frags for ks=0 into buf 0
    int s = 0, ph = 0;
    mbar_wait(mb_full, 0);
    loadA(0, sb + TILES_OFF, 0);

    for (int kt = 0; kt < NKT; kt++) {
        const uint32_t cA = sb + TILES_OFF + s * STAGE_BYTES;
        const uint32_t cB = cA + A_TILE_BYTES;

        #pragma unroll
        for (int ks = 0; ks < 3; ks++) {
            loadB(cB, ks);
            loadA((ks + 1) & 1, cA, ks + 1);   // prefetch next step's A
            mma_batch(ks & 1);
        }
        // ks == 3
        loadB(cB, 3);
        const int s2 = (s + 1 == STAGES) ? 0 : s + 1;
        const int ph2 = (s + 1 == STAGES) ? (ph ^ 1) : ph;
        if (kt + 1 < NKT) {
            mbar_wait(mb_full + 8 * s2, ph2);
            loadA(0, sb + TILES_OFF + s2 * STAGE_BYTES, 0);  // next stage ks=0
        }
        mma_batch(1);
        // Stage release AFTER the final MMA consuming stage-s data.
        if (lane == 0) mbar_arrive(mb_empty + 8 * s);
        s = s2; ph = ph2;
    }

    // epilogue: scale in fp32, streaming float2 stores (write-once data)
    const int erow = mt * BM + warp_m * 32 + (lane >> 2);
    const int ecol = nt * BN + warp_n * 64 + 2 * (lane & 3);
    #pragma unroll
    for (int mi = 0; mi < 2; mi++) {
        #pragma unroll
        for (int ni = 0; ni < 8; ni++) {
            const int r0 = erow + mi * 16;
            const int cc = ecol + ni * 8;
            float2 v01 = make_float2(acc[mi][ni][0] * SCALE, acc[mi][ni][1] * SCALE);
            float2 v23 = make_float2(acc[mi][ni][2] * SCALE, acc[mi][ni][3] * SCALE);
            __stcs(reinterpret_cast<float2*>(C + (size_t)r0 * NDIM + cc), v01);
            __stcs(reinterpret_cast<float2*>(C + (size_t)(r0 + 8) * NDIM + cc), v23);
        }
    }
}

// ---------------------------------------------------------------------------
// kernel_launch
// ---------------------------------------------------------------------------
extern "C" void kernel_launch(void* const* d_in, const int* in_sizes, int n_in,
                              void* d_out, int out_size) {
    const float* x = (const float*)d_in[0];
    const int*   w = (const int*)d_in[1];
    float* out = (float*)d_out;

    void *pW, *pA;
    cudaGetSymbolAddress(&pW, g_W);
    cudaGetSymbolAddress(&pA, g_A);

    k_prep<<<(W_CHUNKS + X_CHUNKS) / 256, 256>>>((const int4*)w, (const float4*)x,
                                                 (uint4*)pW, (uint4*)pA);

    cudaFuncSetAttribute(gemm_kernel, cudaFuncAttributeMaxDynamicSharedMemorySize,
                         SMEM_BYTES);
    dim3 grid(NDIM / BN, MDIM / BM);   // (32, 64)
    gemm_kernel<<<grid, NTHREADS, SMEM_BYTES>>>(out);
}

// round 15
// speedup vs baseline: 1.4666x; 1.4666x over previous
#include <cuda_runtime.h>
#include <cuda_fp16.h>
#include <cstdint>

// ============================================================================
// QuantizedLinear: y[M,N] = (x[M,K] @ W_int8[N,K]^T) / 127
//   M=8192, N=4096, K=4096. sm_103 legacy tensor path.
//
//   Round 14 = Round 12 (best: 594us total) with ZERO-NET-REGISTER A
//   prefetch: B fragments shrink to half-buffers (8 regs, reloaded between
//   ni-half MMA batches), freeing exactly 8 regs for A double-buffering
//   (16 regs). Data-register footprint = 88, identical to r12 -> no spill
//   (ptxas spills anything beyond its preferred allocation; r4/r7/r10/r13).
//   Barrier protocol byte-identical to r12.
// ============================================================================

#define KDIM 4096
#define NDIM 4096
#define MDIM 8192
#define BM   128
#define BN   128
#define BK   64
#define NKT  (KDIM / BK)          // 64
#define STAGES 3

#define A_TILE_BYTES (BM * BK * 2)                  // 16384
#define B_TILE_BYTES (BN * BK * 2)                  // 16384
#define STAGE_BYTES  (A_TILE_BYTES + B_TILE_BYTES)  // 32768
#define TILES_OFF    1024
#define SMEM_BYTES   (TILES_OFF + STAGES * STAGE_BYTES)  // 99328 (x2 < 228K)

#define NTHREADS 288   // 8 compute warps + 1 producer warp

#define SCALE (1.0f / 127.0f)

// pre-swizzled fp16 tile scratch (device globals: allocation-free)
__device__ __half g_W[(size_t)NDIM * KDIM];   // 32 MB, tiles [nt][kt][128x64]
__device__ __half g_A[(size_t)MDIM * KDIM];   // 64 MB, tiles [mt][kt][128x64]

__host__ __device__ __forceinline__ uint32_t swz128(uint32_t off) {
    return off ^ ((off >> 3) & 0x70);
}

__device__ __forceinline__ uint32_t pack_h2(float a, float b) {
    __half2 t;
    t.x = __float2half_rn(a);
    t.y = __float2half_rn(b);
    return *reinterpret_cast<uint32_t*>(&t);
}

// ---------------------------------------------------------------------------
// Merged prep: W int32 -> fp16 tiles, x fp32 -> fp16 tiles (SW128 pre-applied)
// ---------------------------------------------------------------------------
#define W_CHUNKS (NDIM * (KDIM / 8))   // 2097152
#define X_CHUNKS (MDIM * (KDIM / 8))   // 4194304

__global__ void k_prep(const int4* __restrict__ w, const float4* __restrict__ x,
                       uint4* __restrict__ Wt, uint4* __restrict__ At) {
    uint32_t t = blockIdx.x * blockDim.x + threadIdx.x;
    if (t < W_CHUNKS) {
        uint32_t n = t >> 9, cg = t & 511;           // 8-elem chunk along K
        int4 v0 = __ldcs(&w[(size_t)n * 1024 + cg * 2]);
        int4 v1 = __ldcs(&w[(size_t)n * 1024 + cg * 2 + 1]);
        uint4 o;
        o.x = pack_h2((float)v0.x, (float)v0.y);
        o.y = pack_h2((float)v0.z, (float)v0.w);
        o.z = pack_h2((float)v1.x, (float)v1.y);
        o.w = pack_h2((float)v1.z, (float)v1.w);
        uint32_t nt = n >> 7, r = n & 127, kt = cg >> 3, c = cg & 7;
        size_t tile_u4 = ((size_t)nt * NKT + kt) * (B_TILE_BYTES / 16);
        __stcs(&Wt[tile_u4 + (swz128(r * 128 + c * 16) >> 4)], o);
    } else {
        t -= W_CHUNKS;
        uint32_t m = t >> 9, cg = t & 511;
        float4 v0 = __ldcs(&x[(size_t)m * 1024 + cg * 2]);
        float4 v1 = __ldcs(&x[(size_t)m * 1024 + cg * 2 + 1]);
        uint4 o;
        o.x = pack_h2(v0.x, v0.y);
        o.y = pack_h2(v0.z, v0.w);
        o.z = pack_h2(v1.x, v1.y);
        o.w = pack_h2(v1.z, v1.w);
        uint32_t mt = m >> 7, r = m & 127, kt = cg >> 3, c = cg & 7;
        size_t tile_u4 = ((size_t)mt * NKT + kt) * (A_TILE_BYTES / 16);
        __stcs(&At[tile_u4 + (swz128(r * 128 + c * 16) >> 4)], o);
    }
}

// ---------------------------------------------------------------------------
// PTX helpers
// ---------------------------------------------------------------------------
__device__ __forceinline__ bool elect_one() {
    uint32_t pred;
    asm volatile("{\n\t.reg .pred p;\n\telect.sync _|p, 0xFFFFFFFF;\n\t"
                 "selp.b32 %0, 1, 0, p;\n\t}" : "=r"(pred));
    return pred != 0;
}
__device__ __forceinline__ void mbar_init(uint32_t a, uint32_t cnt) {
    asm volatile("mbarrier.init.shared.b64 [%0], %1;" :: "r"(a), "r"(cnt) : "memory");
}
__device__ __forceinline__ void mbar_expect_tx(uint32_t a, uint32_t bytes) {
    asm volatile("mbarrier.arrive.expect_tx.shared.b64 _, [%0], %1;"
                 :: "r"(a), "r"(bytes) : "memory");
}
__device__ __forceinline__ void mbar_arrive(uint32_t a) {
    asm volatile("mbarrier.arrive.shared.b64 _, [%0];" :: "r"(a) : "memory");
}
__device__ __forceinline__ void mbar_wait(uint32_t a, uint32_t parity) {
    asm volatile(
        "{\n\t.reg .pred P1;\n"
        "WAIT_LOOP_%=:\n\t"
        "mbarrier.try_wait.parity.acquire.cta.shared::cta.b64 P1, [%0], %1, 0x989680;\n\t"
        "@P1 bra.uni WAIT_DONE_%=;\n\t"
        "bra.uni WAIT_LOOP_%=;\n"
        "WAIT_DONE_%=:\n\t}"
        :: "r"(a), "r"(parity) : "memory");
}
__device__ __forceinline__ void bulk_g2s(uint32_t dst, const void* src,
                                         uint32_t bytes, uint32_t mbar) {
    asm volatile(
        "cp.async.bulk.shared::cluster.global.mbarrier::complete_tx::bytes "
        "[%0], [%1], %2, [%3];"
        :: "r"(dst), "l"(src), "r"(bytes), "r"(mbar) : "memory");
}
__device__ __forceinline__ void ldmatrix_x4(uint32_t& r0, uint32_t& r1,
                                            uint32_t& r2, uint32_t& r3, uint32_t a) {
    asm volatile("ldmatrix.sync.aligned.m8n8.x4.shared.b16 {%0,%1,%2,%3}, [%4];"
                 : "=r"(r0), "=r"(r1), "=r"(r2), "=r"(r3) : "r"(a));
}
__device__ __forceinline__ void mma16816(float* c, const uint32_t* a, const uint32_t* b) {
    asm volatile(
        "mma.sync.aligned.m16n8k16.row.col.f32.f16.f16.f32 "
        "{%0,%1,%2,%3}, {%4,%5,%6,%7}, {%8,%9}, {%0,%1,%2,%3};"
        : "+f"(c[0]), "+f"(c[1]), "+f"(c[2]), "+f"(c[3])
        : "r"(a[0]), "r"(a[1]), "r"(a[2]), "r"(a[3]), "r"(b[0]), "r"(b[1]));
}

// ---------------------------------------------------------------------------
// GEMM: 288 threads. Warps 0-7 compute (4x2, warp tile 32x64). Warp 8: producer.
// Two CTAs co-resident per SM. A double-buffered, B half-buffered (88 data regs,
// same as r12).
// ---------------------------------------------------------------------------
__global__ __launch_bounds__(NTHREADS, 2)
void gemm_kernel(float* __restrict__ C) {
    extern __shared__ char smem[];
    const uint32_t sb = (uint32_t)__cvta_generic_to_shared(smem);
    const int tid  = threadIdx.x;
    const int warp = tid >> 5;
    const int lane = tid & 31;
    const int nt = blockIdx.x;   // 0..31
    const int mt = blockIdx.y;   // 0..63

    const uint32_t mb_full  = sb;        // 3 x 8B
    const uint32_t mb_empty = sb + 32;   // 3 x 8B

    if (tid == 0) {
        #pragma unroll
        for (int s = 0; s < STAGES; s++) {
            mbar_init(mb_full  + 8 * s, 1);   // tx-based completion
            mbar_init(mb_empty + 8 * s, 8);   // lane0 of each compute warp
        }
    }
    __syncthreads();

    if (warp == 8) {
        // ---------------- producer ----------------
        if (elect_one()) {
            const char* pA = (const char*)g_A + (size_t)mt * NKT * A_TILE_BYTES;
            const char* pB = (const char*)g_W + (size_t)nt * NKT * B_TILE_BYTES;
            int s = 0, ph = 1;
            for (int j = 0; j < NKT; j++) {
                mbar_wait(mb_empty + 8 * s, ph);  // 1st pass free (parity 1)
                const uint32_t st = sb + TILES_OFF + s * STAGE_BYTES;
                mbar_expect_tx(mb_full + 8 * s, STAGE_BYTES);
                bulk_g2s(st, pA + (size_t)j * A_TILE_BYTES, A_TILE_BYTES,
                         mb_full + 8 * s);
                bulk_g2s(st + A_TILE_BYTES, pB + (size_t)j * B_TILE_BYTES,
                         B_TILE_BYTES, mb_full + 8 * s);
                if (++s == STAGES) { s = 0; ph ^= 1; }
            }
        }
        return;
    }

    // ---------------- compute warps ----------------
    const int warp_m = warp >> 1;   // 0..3 -> 32 rows each
    const int warp_n = warp & 1;    // 0..1 -> 64 cols each

    // Swizzle collapses to a per-thread constant XOR: low-offset bits
    // (ks*32 + kofs <= 112) never carry into row bits, and row&7 == lane&7.
    const uint32_t xm = (uint32_t)(lane & 7) << 4;
    const uint32_t aK = (uint32_t)(lane >> 4) * 16;          // k-half for A ldmatrix
    const uint32_t bK = (uint32_t)((lane >> 3) & 1) * 16;    // k-half for B ldmatrix
    const uint32_t aBase = (uint32_t)(warp_m * 32 + (lane & 15)) * 128;
    const uint32_t bBase = (uint32_t)(warp_n * 64 + ((lane >> 4) & 1) * 8 + (lane & 7)) * 128;

    float acc[2][8][4];
    #pragma unroll
    for (int mi = 0; mi < 2; mi++)
        #pragma unroll
        for (int ni = 0; ni < 8; ni++)
            #pragma unroll
            for (int r = 0; r < 4; r++) acc[mi][ni][r] = 0.0f;

    uint32_t afr[2][2][4];   // [buf][mi][reg] - A double buffered (16 regs)
    uint32_t bfr[4][2];      // [nk][reg]      - B HALF buffer (8 regs)

    auto loadA = [&](int b, uint32_t sA, int ks) {
        const uint32_t lowA = ((uint32_t)(ks * 32) + aK) ^ xm;
        #pragma unroll
        for (int mi = 0; mi < 2; mi++)
            ldmatrix_x4(afr[b][mi][0], afr[b][mi][1], afr[b][mi][2], afr[b][mi][3],
                        sA + aBase + mi * (16 * 128) + lowA);
    };
    // load B ni-half h (h=0: ni 0-3, h=1: ni 4-7) into the shared half-buffer
    auto loadBh = [&](int h, uint32_t sB, int ks) {
        const uint32_t lowB = ((uint32_t)(ks * 32) + bK) ^ xm;
        #pragma unroll
        for (int nj = 0; nj < 2; nj++)
            ldmatrix_x4(bfr[2 * nj][0], bfr[2 * nj][1],
                        bfr[2 * nj + 1][0], bfr[2 * nj + 1][1],
                        sB + bBase + (h * 2 + nj) * (16 * 128) + lowB);
    };
    auto mma_half = [&](int b, int h) {
        #pragma unroll
        for (int mi = 0; mi < 2; mi++)
            #pragma unroll
            for (int nk = 0; nk < 4; nk++)
                mma16816(acc[mi][h * 4 + nk], afr[b][mi], bfr[nk]);
    };

    // prologue: stage 0 full, A frags for ks=0 into buf 0
    int s = 0, ph = 0;
    mbar_wait(mb_full, 0);
    loadA(0, sb + TILES_OFF, 0);

    for (int kt = 0; kt < NKT; kt++) {
        const uint32_t cA = sb + TILES_OFF + s * STAGE_BYTES;
        const uint32_t cB = cA + A_TILE_BYTES;

        #pragma unroll
        for (int ks = 0; ks < 4; ks++) {
            const int buf = ks & 1;
            loadBh(0, cB, ks);
            if (ks < 3) loadA(buf ^ 1, cA, ks + 1);   // prefetch next step's A
            mma_half(buf, 0);
            loadBh(1, cB, ks);                        // overlaps mma_half(·,0)
            mma_half(buf, 1);
        }
        // Stage release AFTER the final MMA consuming stage-s data (r12 rule).
        if (lane == 0) mbar_arrive(mb_empty + 8 * s);
        const int s2 = (s + 1 == STAGES) ? 0 : s + 1;
        const int ph2 = (s + 1 == STAGES) ? (ph ^ 1) : ph;
        if (kt + 1 < NKT) {
            mbar_wait(mb_full + 8 * s2, ph2);
            loadA(0, sb + TILES_OFF + s2 * STAGE_BYTES, 0);  // next stage ks=0
        }
        s = s2; ph = ph2;
    }

    // epilogue: scale in fp32, streaming float2 stores (write-once data)
    const int erow = mt * BM + warp_m * 32 + (lane >> 2);
    const int ecol = nt * BN + warp_n * 64 + 2 * (lane & 3);
    #pragma unroll
    for (int mi = 0; mi < 2; mi++) {
        #pragma unroll
        for (int ni = 0; ni < 8; ni++) {
            const int r0 = erow + mi * 16;
            const int cc = ecol + ni * 8;
            float2 v01 = make_float2(acc[mi][ni][0] * SCALE, acc[mi][ni][1] * SCALE);
            float2 v23 = make_float2(acc[mi][ni][2] * SCALE, acc[mi][ni][3] * SCALE);
            __stcs(reinterpret_cast<float2*>(C + (size_t)r0 * NDIM + cc), v01);
            __stcs(reinterpret_cast<float2*>(C + (size_t)(r0 + 8) * NDIM + cc), v23);
        }
    }
}

// ---------------------------------------------------------------------------
// kernel_launch
// ---------------------------------------------------------------------------
extern "C" void kernel_launch(void* const* d_in, const int* in_sizes, int n_in,
                              void* d_out, int out_size) {
    const float* x = (const float*)d_in[0];
    const int*   w = (const int*)d_in[1];
    float* out = (float*)d_out;

    void *pW, *pA;
    cudaGetSymbolAddress(&pW, g_W);
    cudaGetSymbolAddress(&pA, g_A);

    k_prep<<<(W_CHUNKS + X_CHUNKS) / 256, 256>>>((const int4*)w, (const float4*)x,
                                                 (uint4*)pW, (uint4*)pA);

    cudaFuncSetAttribute(gemm_kernel, cudaFuncAttributeMaxDynamicSharedMemorySize,
                         SMEM_BYTES);
    dim3 grid(NDIM / BN, MDIM / BM);   // (32, 64)
    gemm_kernel<<<grid, NTHREADS, SMEM_BYTES>>>(out);
}

// round 17
// speedup vs baseline: 1.5516x; 1.0580x over previous
#include <cuda_runtime.h>
#include <cuda_fp16.h>
#include <cstdint>

// ============================================================================
// QuantizedLinear: y[M,N] = (x[M,K] @ W_int8[N,K]^T) / 127
//   M=8192, N=4096, K=4096. sm_103 legacy tensor path.
//
//   Round 15 = Round 12 verbatim (the measured optimum: 594.0us total /
//   556.3 GEMM, tensor 81.9%, rt_eff 8.26 vs floor 8) with ONE issue-order
//   tweak: B fragment loads issue before A loads in the ks body (B's
//   longer LDSM chain fronted -> full latency overlap). No register,
//   barrier, or dataflow change. Closed levers (evidence): tcgen05
//   (toolchain), reg buffering (r13 spill / r14 WAR), >4 warps/SMSP (r5),
//   3 CTAs (r8/r9), deeper stages (smem cap).
// ============================================================================

#define KDIM 4096
#define NDIM 4096
#define MDIM 8192
#define BM   128
#define BN   128
#define BK   64
#define NKT  (KDIM / BK)          // 64
#define STAGES 3

#define A_TILE_BYTES (BM * BK * 2)                  // 16384
#define B_TILE_BYTES (BN * BK * 2)                  // 16384
#define STAGE_BYTES  (A_TILE_BYTES + B_TILE_BYTES)  // 32768
#define TILES_OFF    1024
#define SMEM_BYTES   (TILES_OFF + STAGES * STAGE_BYTES)  // 99328 (x2 < 228K)

#define NTHREADS 288   // 8 compute warps + 1 producer warp

#define SCALE (1.0f / 127.0f)

// pre-swizzled fp16 tile scratch (device globals: allocation-free)
__device__ __half g_W[(size_t)NDIM * KDIM];   // 32 MB, tiles [nt][kt][128x64]
__device__ __half g_A[(size_t)MDIM * KDIM];   // 64 MB, tiles [mt][kt][128x64]

__host__ __device__ __forceinline__ uint32_t swz128(uint32_t off) {
    return off ^ ((off >> 3) & 0x70);
}

__device__ __forceinline__ uint32_t pack_h2(float a, float b) {
    __half2 t;
    t.x = __float2half_rn(a);
    t.y = __float2half_rn(b);
    return *reinterpret_cast<uint32_t*>(&t);
}

// ---------------------------------------------------------------------------
// Merged prep: W int32 -> fp16 tiles, x fp32 -> fp16 tiles (SW128 pre-applied)
// Streaming loads/stores: all data here is touched exactly once.
// ---------------------------------------------------------------------------
#define W_CHUNKS (NDIM * (KDIM / 8))   // 2097152
#define X_CHUNKS (MDIM * (KDIM / 8))   // 4194304

__global__ void k_prep(const int4* __restrict__ w, const float4* __restrict__ x,
                       uint4* __restrict__ Wt, uint4* __restrict__ At) {
    uint32_t t = blockIdx.x * blockDim.x + threadIdx.x;
    if (t < W_CHUNKS) {
        uint32_t n = t >> 9, cg = t & 511;           // 8-elem chunk along K
        int4 v0 = __ldcs(&w[(size_t)n * 1024 + cg * 2]);
        int4 v1 = __ldcs(&w[(size_t)n * 1024 + cg * 2 + 1]);
        uint4 o;
        o.x = pack_h2((float)v0.x, (float)v0.y);
        o.y = pack_h2((float)v0.z, (float)v0.w);
        o.z = pack_h2((float)v1.x, (float)v1.y);
        o.w = pack_h2((float)v1.z, (float)v1.w);
        uint32_t nt = n >> 7, r = n & 127, kt = cg >> 3, c = cg & 7;
        size_t tile_u4 = ((size_t)nt * NKT + kt) * (B_TILE_BYTES / 16);
        __stcs(&Wt[tile_u4 + (swz128(r * 128 + c * 16) >> 4)], o);
    } else {
        t -= W_CHUNKS;
        uint32_t m = t >> 9, cg = t & 511;
        float4 v0 = __ldcs(&x[(size_t)m * 1024 + cg * 2]);
        float4 v1 = __ldcs(&x[(size_t)m * 1024 + cg * 2 + 1]);
        uint4 o;
        o.x = pack_h2(v0.x, v0.y);
        o.y = pack_h2(v0.z, v0.w);
        o.z = pack_h2(v1.x, v1.y);
        o.w = pack_h2(v1.z, v1.w);
        uint32_t mt = m >> 7, r = m & 127, kt = cg >> 3, c = cg & 7;
        size_t tile_u4 = ((size_t)mt * NKT + kt) * (A_TILE_BYTES / 16);
        __stcs(&At[tile_u4 + (swz128(r * 128 + c * 16) >> 4)], o);
    }
}

// ---------------------------------------------------------------------------
// PTX helpers
// ---------------------------------------------------------------------------
__device__ __forceinline__ bool elect_one() {
    uint32_t pred;
    asm volatile("{\n\t.reg .pred p;\n\telect.sync _|p, 0xFFFFFFFF;\n\t"
                 "selp.b32 %0, 1, 0, p;\n\t}" : "=r"(pred));
    return pred != 0;
}
__device__ __forceinline__ void mbar_init(uint32_t a, uint32_t cnt) {
    asm volatile("mbarrier.init.shared.b64 [%0], %1;" :: "r"(a), "r"(cnt) : "memory");
}
__device__ __forceinline__ void mbar_expect_tx(uint32_t a, uint32_t bytes) {
    asm volatile("mbarrier.arrive.expect_tx.shared.b64 _, [%0], %1;"
                 :: "r"(a), "r"(bytes) : "memory");
}
__device__ __forceinline__ void mbar_arrive(uint32_t a) {
    asm volatile("mbarrier.arrive.shared.b64 _, [%0];" :: "r"(a) : "memory");
}
__device__ __forceinline__ void mbar_wait(uint32_t a, uint32_t parity) {
    asm volatile(
        "{\n\t.reg .pred P1;\n"
        "WAIT_LOOP_%=:\n\t"
        "mbarrier.try_wait.parity.acquire.cta.shared::cta.b64 P1, [%0], %1, 0x989680;\n\t"
        "@P1 bra.uni WAIT_DONE_%=;\n\t"
        "bra.uni WAIT_LOOP_%=;\n"
        "WAIT_DONE_%=:\n\t}"
        :: "r"(a), "r"(parity) : "memory");
}
__device__ __forceinline__ void bulk_g2s(uint32_t dst, const void* src,
                                         uint32_t bytes, uint32_t mbar) {
    asm volatile(
        "cp.async.bulk.shared::cluster.global.mbarrier::complete_tx::bytes "
        "[%0], [%1], %2, [%3];"
        :: "r"(dst), "l"(src), "r"(bytes), "r"(mbar) : "memory");
}
__device__ __forceinline__ void ldmatrix_x4(uint32_t& r0, uint32_t& r1,
                                            uint32_t& r2, uint32_t& r3, uint32_t a) {
    asm volatile("ldmatrix.sync.aligned.m8n8.x4.shared.b16 {%0,%1,%2,%3}, [%4];"
                 : "=r"(r0), "=r"(r1), "=r"(r2), "=r"(r3) : "r"(a));
}
__device__ __forceinline__ void mma16816(float* c, const uint32_t* a, const uint32_t* b) {
    asm volatile(
        "mma.sync.aligned.m16n8k16.row.col.f32.f16.f16.f32 "
        "{%0,%1,%2,%3}, {%4,%5,%6,%7}, {%8,%9}, {%0,%1,%2,%3};"
        : "+f"(c[0]), "+f"(c[1]), "+f"(c[2]), "+f"(c[3])
        : "r"(a[0]), "r"(a[1]), "r"(a[2]), "r"(a[3]), "r"(b[0]), "r"(b[1]));
}

// ---------------------------------------------------------------------------
// GEMM: 288 threads. Warps 0-7 compute (4x2, warp tile 32x64). Warp 8: producer.
// Two CTAs co-resident per SM -> 4 compute warps/SMSP, 2 from each CTA.
// ---------------------------------------------------------------------------
__global__ __launch_bounds__(NTHREADS, 2)
void gemm_kernel(float* __restrict__ C) {
    extern __shared__ char smem[];
    const uint32_t sb = (uint32_t)__cvta_generic_to_shared(smem);
    const int tid  = threadIdx.x;
    const int warp = tid >> 5;
    const int lane = tid & 31;
    const int nt = blockIdx.x;   // 0..31
    const int mt = blockIdx.y;   // 0..63

    const uint32_t mb_full  = sb;        // 3 x 8B
    const uint32_t mb_empty = sb + 32;   // 3 x 8B

    if (tid == 0) {
        #pragma unroll
        for (int s = 0; s < STAGES; s++) {
            mbar_init(mb_full  + 8 * s, 1);   // tx-based completion
            mbar_init(mb_empty + 8 * s, 8);   // lane0 of each compute warp
        }
    }
    __syncthreads();

    if (warp == 8) {
        // ---------------- producer ----------------
        if (elect_one()) {
            const char* pA = (const char*)g_A + (size_t)mt * NKT * A_TILE_BYTES;
            const char* pB = (const char*)g_W + (size_t)nt * NKT * B_TILE_BYTES;
            int s = 0, ph = 1;
            for (int j = 0; j < NKT; j++) {
                mbar_wait(mb_empty + 8 * s, ph);  // 1st pass free (parity 1)
                const uint32_t st = sb + TILES_OFF + s * STAGE_BYTES;
                mbar_expect_tx(mb_full + 8 * s, STAGE_BYTES);
                bulk_g2s(st, pA + (size_t)j * A_TILE_BYTES, A_TILE_BYTES,
                         mb_full + 8 * s);
                bulk_g2s(st + A_TILE_BYTES, pB + (size_t)j * B_TILE_BYTES,
                         B_TILE_BYTES, mb_full + 8 * s);
                if (++s == STAGES) { s = 0; ph ^= 1; }
            }
        }
        return;
    }

    // ---------------- compute warps ----------------
    const int warp_m = warp >> 1;   // 0..3 -> 32 rows each
    const int warp_n = warp & 1;    // 0..1 -> 64 cols each

    // Swizzle collapses to a per-thread constant XOR: low-offset bits
    // (ks*32 + kofs <= 112) never carry into row bits, and row&7 == lane&7.
    const uint32_t xm = (uint32_t)(lane & 7) << 4;
    const uint32_t aK = (uint32_t)(lane >> 4) * 16;          // k-half for A ldmatrix
    const uint32_t bK = (uint32_t)((lane >> 3) & 1) * 16;    // k-half for B ldmatrix
    const uint32_t aBase = (uint32_t)(warp_m * 32 + (lane & 15)) * 128;
    const uint32_t bBase = (uint32_t)(warp_n * 64 + ((lane >> 4) & 1) * 8 + (lane & 7)) * 128;

    float acc[2][8][4];
    #pragma unroll
    for (int mi = 0; mi < 2; mi++)
        #pragma unroll
        for (int ni = 0; ni < 8; ni++)
            #pragma unroll
            for (int r = 0; r < 4; r++) acc[mi][ni][r] = 0.0f;

    uint32_t afr[2][4];   // [mi][reg]
    uint32_t bfr[8][2];   // [ni][reg]

    int s = 0, ph = 0;
    for (int kt = 0; kt < NKT; kt++) {
        mbar_wait(mb_full + 8 * s, ph);
        const uint32_t sA = sb + TILES_OFF + s * STAGE_BYTES;
        const uint32_t sB = sA + A_TILE_BYTES;

        #pragma unroll
        for (int ks = 0; ks < 4; ks++) {
            const uint32_t lowA = ((uint32_t)(ks * 32) + aK) ^ xm;
            const uint32_t lowB = ((uint32_t)(ks * 32) + bK) ^ xm;
            // B first: its longer 4-LDSM chain fronts the scoreboard,
            // overlapping fully with the A chain.
            #pragma unroll
            for (int nj = 0; nj < 4; nj++)
                ldmatrix_x4(bfr[2 * nj][0], bfr[2 * nj][1],
                            bfr[2 * nj + 1][0], bfr[2 * nj + 1][1],
                            sB + bBase + nj * (16 * 128) + lowB);
            #pragma unroll
            for (int mi = 0; mi < 2; mi++)
                ldmatrix_x4(afr[mi][0], afr[mi][1], afr[mi][2], afr[mi][3],
                            sA + aBase + mi * (16 * 128) + lowA);
            #pragma unroll
            for (int mi = 0; mi < 2; mi++)
                #pragma unroll
                for (int ni = 0; ni < 8; ni++)
                    mma16816(acc[mi][ni], afr[mi], bfr[ni]);
        }
        // Stage release AFTER the final MMA batch (proven r6/r12 placement).
        if (lane == 0) mbar_arrive(mb_empty + 8 * s);
        if (++s == STAGES) { s = 0; ph ^= 1; }
    }

    // epilogue: scale in fp32, streaming float2 stores (write-once data)
    const int erow = mt * BM + warp_m * 32 + (lane >> 2);
    const int ecol = nt * BN + warp_n * 64 + 2 * (lane & 3);
    #pragma unroll
    for (int mi = 0; mi < 2; mi++) {
        #pragma unroll
        for (int ni = 0; ni < 8; ni++) {
            const int r0 = erow + mi * 16;
            const int cc = ecol + ni * 8;
            float2 v01 = make_float2(acc[mi][ni][0] * SCALE, acc[mi][ni][1] * SCALE);
            float2 v23 = make_float2(acc[mi][ni][2] * SCALE, acc[mi][ni][3] * SCALE);
            __stcs(reinterpret_cast<float2*>(C + (size_t)r0 * NDIM + cc), v01);
            __stcs(reinterpret_cast<float2*>(C + (size_t)(r0 + 8) * NDIM + cc), v23);
        }
    }
}

// ---------------------------------------------------------------------------
// kernel_launch
// ---------------------------------------------------------------------------
extern "C" void kernel_launch(void* const* d_in, const int* in_sizes, int n_in,
                              void* d_out, int out_size) {
    const float* x = (const float*)d_in[0];
    const int*   w = (const int*)d_in[1];
    float* out = (float*)d_out;

    void *pW, *pA;
    cudaGetSymbolAddress(&pW, g_W);
    cudaGetSymbolAddress(&pA, g_A);

    k_prep<<<(W_CHUNKS + X_CHUNKS) / 256, 256>>>((const int4*)w, (const float4*)x,
                                                 (uint4*)pW, (uint4*)pA);

    cudaFuncSetAttribute(gemm_kernel, cudaFuncAttributeMaxDynamicSharedMemorySize,
                         SMEM_BYTES);
    dim3 grid(NDIM / BN, MDIM / BM);   // (32, 64)
    gemm_kernel<<<grid, NTHREADS, SMEM_BYTES>>>(out);
}